// round 1
// baseline (speedup 1.0000x reference)
#include <cuda_runtime.h>
#include <cstdint>
#include <math.h>

// Problem constants
#define BB   64
#define NN   257
#define DD   1024
#define HH   16
#define HD   64
#define MROWS (BB*NN)          // 16448
#define QKV_SLAB ((size_t)BB*HH*NN*HD)  // 16,842,752 floats per q/k/v slab

// Scratch (device globals — no allocation allowed)
__device__ float g_qkv[3ULL * BB * HH * NN * HD];   // [3, B, H, N, HD]
__device__ float g_attn_out[(size_t)MROWS * DD];    // [B*N, D]
__device__ int   g_mask_mode;                       // 0=u8, 1=i32, 2=f32, 3=bf16

// ---------------------------------------------------------------------------
// Mask dtype detector: inspect first 1KB byte pattern (deterministic).
// u8 bool: values 0/1 at every offset. i32: 0/1 only at offset%4==0.
// f32 1.0f bytes = {00,00,80,3F} (0x3F at offset%4==3). bf16 1.0 = {80,3F}
// (0x3F at odd offsets incl. offset%4==1, which f32 never produces).
// ---------------------------------------------------------------------------
__global__ void detect_mask_kernel(const unsigned char* __restrict__ p) {
    if (threadIdx.x != 0 || blockIdx.x != 0) return;
    bool bf16 = false, f32 = false, u8 = false;
    for (int i = 0; i < 1024; i++) {
        unsigned char v = p[i];
        if (v == 0x3F) {
            if ((i & 3) == 1) bf16 = true; else f32 = true;
        } else if (v == 1 && (i & 3) != 0) {
            u8 = true;
        }
    }
    g_mask_mode = bf16 ? 3 : (f32 ? 2 : (u8 ? 0 : 1));
}

// ---------------------------------------------------------------------------
// NT SGEMM: C[m,e] = sum_k A[m,k]*W[e,k] + bias[e]
// A: [M,K] row-major, W: [Nn,K] row-major. 128x128 tile, BK=16, 8x8/thread.
// mode 0: plain write to C.  mode 1: scatter into g_qkv [3,B,H,N,HD].
// ---------------------------------------------------------------------------
#define BM 128
#define BN 128
#define BK 16

__global__ __launch_bounds__(256, 2)
void gemm_nt(const float* __restrict__ A, const float* __restrict__ W,
             const float* __restrict__ bias, float* __restrict__ C,
             int M, int Nn, int K, int mode)
{
    __shared__ float As[BK][BM];
    __shared__ float Bs[BK][BN];

    const int tid = threadIdx.x;
    const int tx = tid & 15;        // 0..15 -> output cols tx*8..+7
    const int ty = tid >> 4;        // 0..15 -> output rows ty*8..+7
    const int mBase = blockIdx.y * BM;
    const int nBase = blockIdx.x * BN;

    float acc[8][8];
    #pragma unroll
    for (int i = 0; i < 8; i++)
        #pragma unroll
        for (int j = 0; j < 8; j++) acc[i][j] = 0.f;

    for (int kb = 0; kb < K; kb += BK) {
        // Load A/B tiles: 512 float4 each, 2 per thread
        #pragma unroll
        for (int it = 0; it < 2; it++) {
            int idx = tid + it * 256;         // 0..511
            int row = idx >> 2;               // 0..127
            int kq  = (idx & 3) << 2;         // 0,4,8,12
            int gm  = mBase + row;
            float4 av = (gm < M)
                ? *(const float4*)(A + (size_t)gm * K + kb + kq)
                : make_float4(0.f, 0.f, 0.f, 0.f);
            As[kq + 0][row] = av.x;
            As[kq + 1][row] = av.y;
            As[kq + 2][row] = av.z;
            As[kq + 3][row] = av.w;
            float4 bv = *(const float4*)(W + (size_t)(nBase + row) * K + kb + kq);
            Bs[kq + 0][row] = bv.x;
            Bs[kq + 1][row] = bv.y;
            Bs[kq + 2][row] = bv.z;
            Bs[kq + 3][row] = bv.w;
        }
        __syncthreads();

        #pragma unroll
        for (int k = 0; k < BK; k++) {
            float4 a0 = *(const float4*)&As[k][ty * 8];
            float4 a1 = *(const float4*)&As[k][ty * 8 + 4];
            float4 b0 = *(const float4*)&Bs[k][tx * 8];
            float4 b1 = *(const float4*)&Bs[k][tx * 8 + 4];
            float a[8] = {a0.x, a0.y, a0.z, a0.w, a1.x, a1.y, a1.z, a1.w};
            float b[8] = {b0.x, b0.y, b0.z, b0.w, b1.x, b1.y, b1.z, b1.w};
            #pragma unroll
            for (int i = 0; i < 8; i++)
                #pragma unroll
                for (int j = 0; j < 8; j++)
                    acc[i][j] = fmaf(a[i], b[j], acc[i][j]);
        }
        __syncthreads();
    }

    // Epilogue
    #pragma unroll
    for (int i = 0; i < 8; i++) {
        int m = mBase + ty * 8 + i;
        if (m >= M) continue;
        int bidx = m / NN;
        int nidx = m - bidx * NN;
        #pragma unroll
        for (int j = 0; j < 8; j++) {
            int e = nBase + tx * 8 + j;
            float v = acc[i][j] + bias[e];
            if (mode == 0) {
                C[(size_t)m * Nn + e] = v;
            } else {
                int qi  = e >> 10;       // 0..2
                int rem = e & 1023;
                int h   = rem >> 6;      // 0..15
                int hd  = rem & 63;
                g_qkv[((((size_t)qi * BB + bidx) * HH + h) * NN + nidx) * HD + hd] = v;
            }
        }
    }
}

// ---------------------------------------------------------------------------
// Attention: one CTA per (b,h). K,V in smem, one warp per query, online
// softmax. Writes [B*N, D] directly for the output projection.
// ---------------------------------------------------------------------------
#define ATTN_SMEM_BYTES ((2 * NN * HD + NN + 4) * (int)sizeof(float))

__global__ __launch_bounds__(256)
void attn_kernel(const unsigned char* __restrict__ mask_raw)
{
    extern __shared__ float sh[];
    float* Ks  = sh;                  // [257][64]
    float* Vs  = sh + NN * HD;        // [257][64]
    float* msk = sh + 2 * NN * HD;    // [257] additive mask (0 or -1e30)

    const int tid = threadIdx.x;
    const int bh  = blockIdx.x;
    const int b   = bh >> 4;
    const int h   = bh & 15;

    const float* Qg = g_qkv + ((size_t)b * HH + h) * NN * HD;
    const float* Kg = Qg + QKV_SLAB;
    const float* Vg = Kg + QKV_SLAB;

    // Stage K,V (257*16 float4 each)
    const float4* Kg4 = (const float4*)Kg;
    const float4* Vg4 = (const float4*)Vg;
    for (int i = tid; i < NN * (HD / 4); i += 256) {
        ((float4*)Ks)[i] = Kg4[i];
        ((float4*)Vs)[i] = Vg4[i];
    }

    const int mode = g_mask_mode;
    for (int j = tid; j < NN; j += 256) {
        int idx = b * NN + j;
        bool m;
        if      (mode == 0) m = mask_raw[idx] != 0;
        else if (mode == 1) m = ((const int*)mask_raw)[idx] != 0;
        else if (mode == 2) m = ((const float*)mask_raw)[idx] != 0.f;
        else                m = ((const unsigned short*)mask_raw)[idx] != 0;
        msk[j] = m ? -1e30f : 0.f;
    }
    __syncthreads();

    const int warp = tid >> 5;
    const int lane = tid & 31;

    for (int q = warp; q < NN; q += 8) {
        float2 qv = ((const float2*)(Qg + q * HD))[lane];
        float mmax = -INFINITY, denom = 0.f, acc0 = 0.f, acc1 = 0.f;
        for (int j = 0; j < NN; j++) {
            float2 kv = ((const float2*)(Ks + j * HD))[lane];
            float part = qv.x * kv.x + qv.y * kv.y;
            part += __shfl_xor_sync(0xffffffffu, part, 16);
            part += __shfl_xor_sync(0xffffffffu, part, 8);
            part += __shfl_xor_sync(0xffffffffu, part, 4);
            part += __shfl_xor_sync(0xffffffffu, part, 2);
            part += __shfl_xor_sync(0xffffffffu, part, 1);
            float s = part * 0.125f + msk[j];          // 1/sqrt(64)
            float mnew = fmaxf(mmax, s);
            float c = __expf(mmax - mnew);             // 0 on first iter
            float p = __expf(s - mnew);
            float2 vv = ((const float2*)(Vs + j * HD))[lane];
            acc0  = acc0 * c + p * vv.x;
            acc1  = acc1 * c + p * vv.y;
            denom = denom * c + p;
            mmax  = mnew;
        }
        float inv = 1.f / denom;
        float2 o = make_float2(acc0 * inv, acc1 * inv);
        ((float2*)(g_attn_out + (size_t)(b * NN + q) * DD + h * HD))[lane] = o;
    }
}

// ---------------------------------------------------------------------------
extern "C" void kernel_launch(void* const* d_in, const int* in_sizes, int n_in,
                              void* d_out, int out_size)
{
    const float* x            = (const float*)d_in[0];
    const unsigned char* mask = (const unsigned char*)d_in[1];
    const float* in_proj_w    = (const float*)d_in[2];
    const float* in_proj_b    = (const float*)d_in[3];
    const float* out_proj_w   = (const float*)d_in[4];
    const float* out_proj_b   = (const float*)d_in[5];
    float* out = (float*)d_out;

    void* attn_out_ptr = nullptr;
    cudaGetSymbolAddress(&attn_out_ptr, g_attn_out);

    cudaFuncSetAttribute(attn_kernel,
                         cudaFuncAttributeMaxDynamicSharedMemorySize,
                         ATTN_SMEM_BYTES);

    // 1) mask dtype detection (tiny, deterministic)
    detect_mask_kernel<<<1, 32>>>(mask);

    // 2) QKV projection: [16448,1024] x [3072,1024]^T -> scattered [3,B,H,N,HD]
    {
        dim3 grid(3 * DD / BN, (MROWS + BM - 1) / BM);
        gemm_nt<<<grid, 256>>>(x, in_proj_w, in_proj_b, nullptr,
                               MROWS, 3 * DD, DD, 1);
    }

    // 3) attention per (b,h)
    attn_kernel<<<BB * HH, 256, ATTN_SMEM_BYTES>>>(mask);

    // 4) output projection: [16448,1024] x [1024,1024]^T -> d_out
    {
        dim3 grid(DD / BN, (MROWS + BM - 1) / BM);
        gemm_nt<<<grid, 256>>>((const float*)attn_out_ptr, out_proj_w,
                               out_proj_b, out, MROWS, DD, DD, 0);
    }
}

// round 2
// speedup vs baseline: 2.0219x; 2.0219x over previous
#include <cuda_runtime.h>
#include <cstdint>
#include <math.h>

// Problem constants
#define BB   64
#define NN   257
#define DD   1024
#define HH   16
#define HD   64
#define MROWS (BB*NN)          // 16448
#define QKV_SLAB ((size_t)BB*HH*NN*HD)  // floats per q/k/v slab

// Scratch (device globals — no allocation allowed)
__device__ float g_qkv[3ULL * BB * HH * NN * HD];   // [3, B, H, N, HD]
__device__ float g_attn_out[(size_t)MROWS * DD];    // [B*N, D]
__device__ int   g_mask_mode;                       // 0=u8, 1=i32, 2=f32, 3=bf16

// ---------------------------------------------------------------------------
// Mask dtype detector (unchanged, proven)
// ---------------------------------------------------------------------------
__global__ void detect_mask_kernel(const unsigned char* __restrict__ p) {
    if (threadIdx.x != 0 || blockIdx.x != 0) return;
    bool bf16 = false, f32 = false, u8 = false;
    for (int i = 0; i < 1024; i++) {
        unsigned char v = p[i];
        if (v == 0x3F) {
            if ((i & 3) == 1) bf16 = true; else f32 = true;
        } else if (v == 1 && (i & 3) != 0) {
            u8 = true;
        }
    }
    g_mask_mode = bf16 ? 3 : (f32 ? 2 : (u8 ? 0 : 1));
}

// ---------------------------------------------------------------------------
// NT SGEMM with register prefetch (software pipeline).
// C[m,e] = sum_k A[m,k]*W[e,k] + bias[e]
// ---------------------------------------------------------------------------
#define BM 128
#define BN 128
#define BK 16

__global__ __launch_bounds__(256, 2)
void gemm_nt(const float* __restrict__ A, const float* __restrict__ W,
             const float* __restrict__ bias, float* __restrict__ C,
             int M, int Nn, int K, int mode)
{
    __shared__ float As[BK][BM];
    __shared__ float Bs[BK][BN];

    const int tid = threadIdx.x;
    const int tx = tid & 15;
    const int ty = tid >> 4;
    const int mBase = blockIdx.y * BM;
    const int nBase = blockIdx.x * BN;

    // Per-thread load coordinates (2 float4 loads per tile per operand)
    int rowL[2], kqL[2], gmL[2];
    #pragma unroll
    for (int it = 0; it < 2; it++) {
        int idx = tid + it * 256;
        rowL[it] = idx >> 2;
        kqL[it]  = (idx & 3) << 2;
        gmL[it]  = mBase + rowL[it];
    }

    float acc[8][8];
    #pragma unroll
    for (int i = 0; i < 8; i++)
        #pragma unroll
        for (int j = 0; j < 8; j++) acc[i][j] = 0.f;

    float4 pa[2], pb[2];
    // Prologue: fetch chunk 0 into registers
    #pragma unroll
    for (int it = 0; it < 2; it++) {
        pa[it] = (gmL[it] < M)
            ? *(const float4*)(A + (size_t)gmL[it] * K + kqL[it])
            : make_float4(0.f, 0.f, 0.f, 0.f);
        pb[it] = *(const float4*)(W + (size_t)(nBase + rowL[it]) * K + kqL[it]);
    }

    for (int kb = 0; kb < K; kb += BK) {
        // Commit prefetched registers to smem
        #pragma unroll
        for (int it = 0; it < 2; it++) {
            int row = rowL[it], kq = kqL[it];
            As[kq + 0][row] = pa[it].x;
            As[kq + 1][row] = pa[it].y;
            As[kq + 2][row] = pa[it].z;
            As[kq + 3][row] = pa[it].w;
            Bs[kq + 0][row] = pb[it].x;
            Bs[kq + 1][row] = pb[it].y;
            Bs[kq + 2][row] = pb[it].z;
            Bs[kq + 3][row] = pb[it].w;
        }
        __syncthreads();

        // Prefetch next chunk (LDG latency overlapped with FFMA below)
        if (kb + BK < K) {
            #pragma unroll
            for (int it = 0; it < 2; it++) {
                pa[it] = (gmL[it] < M)
                    ? *(const float4*)(A + (size_t)gmL[it] * K + kb + BK + kqL[it])
                    : make_float4(0.f, 0.f, 0.f, 0.f);
                pb[it] = *(const float4*)(W + (size_t)(nBase + rowL[it]) * K + kb + BK + kqL[it]);
            }
        }

        #pragma unroll
        for (int k = 0; k < BK; k++) {
            float4 a0 = *(const float4*)&As[k][ty * 8];
            float4 a1 = *(const float4*)&As[k][ty * 8 + 4];
            float4 b0 = *(const float4*)&Bs[k][tx * 8];
            float4 b1 = *(const float4*)&Bs[k][tx * 8 + 4];
            float a[8] = {a0.x, a0.y, a0.z, a0.w, a1.x, a1.y, a1.z, a1.w};
            float b[8] = {b0.x, b0.y, b0.z, b0.w, b1.x, b1.y, b1.z, b1.w};
            #pragma unroll
            for (int i = 0; i < 8; i++)
                #pragma unroll
                for (int j = 0; j < 8; j++)
                    acc[i][j] = fmaf(a[i], b[j], acc[i][j]);
        }
        __syncthreads();
    }

    // Epilogue
    #pragma unroll
    for (int i = 0; i < 8; i++) {
        int m = mBase + ty * 8 + i;
        if (m >= M) continue;
        int bidx = m / NN;
        int nidx = m - bidx * NN;
        #pragma unroll
        for (int j = 0; j < 8; j++) {
            int e = nBase + tx * 8 + j;
            float v = acc[i][j] + bias[e];
            if (mode == 0) {
                C[(size_t)m * Nn + e] = v;
            } else {
                int qi  = e >> 10;
                int rem = e & 1023;
                int h   = rem >> 6;
                int hd  = rem & 63;
                g_qkv[((((size_t)qi * BB + bidx) * HH + h) * NN + nidx) * HD + hd] = v;
            }
        }
    }
}

// ---------------------------------------------------------------------------
// Attention v2: one CTA per (b,h), one THREAD per query.
//  - deterministic warp-scan compaction of active (unmasked) keys (~50% skip)
//  - shift-softmax: p = exp(s/8 - 12), no running max / no rescale
//  - K,V broadcast from smem via float4 (conflict-free)
// ---------------------------------------------------------------------------
#define ATTN_THREADS 288
#define ATTN2_SMEM ((2 * NN * HD + NN + 8) * (int)sizeof(float))

__global__ __launch_bounds__(ATTN_THREADS, 1)
void attn_kernel2(const unsigned char* __restrict__ mask_raw)
{
    extern __shared__ float sh[];
    float* Ks   = sh;                    // [257][64]
    float* Vs   = sh + NN * HD;          // [257][64]
    int*   idxl = (int*)(sh + 2 * NN * HD); // [257] active key indices
    __shared__ int s_nact;

    const int tid = threadIdx.x;
    const int bh  = blockIdx.x;
    const int b   = bh >> 4;
    const int h   = bh & 15;

    const float* Qg = g_qkv + ((size_t)b * HH + h) * NN * HD;
    const float* Kg = Qg + QKV_SLAB;
    const float* Vg = Kg + QKV_SLAB;

    // Stage K,V (coalesced float4)
    for (int i = tid; i < NN * (HD / 4); i += ATTN_THREADS) {
        ((float4*)Ks)[i] = ((const float4*)Kg)[i];
        ((float4*)Vs)[i] = ((const float4*)Vg)[i];
    }

    // Deterministic ordered compaction of active keys (warp 0 only)
    if (tid < 32) {
        const int mode = g_mask_mode;
        int count = 0;
        for (int base = 0; base < NN; base += 32) {
            int j = base + tid;
            bool act = false;
            if (j < NN) {
                int idx = b * NN + j;
                bool m;
                if      (mode == 0) m = mask_raw[idx] != 0;
                else if (mode == 1) m = ((const int*)mask_raw)[idx] != 0;
                else if (mode == 2) m = ((const float*)mask_raw)[idx] != 0.f;
                else                m = ((const unsigned short*)mask_raw)[idx] != 0;
                act = !m;   // active = NOT masked
            }
            unsigned bal = __ballot_sync(0xffffffffu, act);
            int pre = __popc(bal & ((1u << tid) - 1u));
            if (act) idxl[count + pre] = j;
            count += __popc(bal);
        }
        if (tid == 0) s_nact = count;
    }
    __syncthreads();
    const int nact = s_nact;

    if (tid < NN) {
        // Q row into registers
        float q[64];
        const float4* Qr = (const float4*)(Qg + tid * HD);
        #pragma unroll
        for (int i = 0; i < 16; i++) {
            float4 t4 = Qr[i];
            q[4*i] = t4.x; q[4*i+1] = t4.y; q[4*i+2] = t4.z; q[4*i+3] = t4.w;
        }
        float acc[64];
        #pragma unroll
        for (int i = 0; i < 64; i++) acc[i] = 0.f;
        float denom = 0.f;

        for (int ii = 0; ii < nact; ii++) {
            int j = idxl[ii];
            const float4* Kr = (const float4*)(Ks + j * HD);
            float s0 = 0.f, s1 = 0.f, s2 = 0.f, s3 = 0.f;
            #pragma unroll
            for (int d = 0; d < 16; d++) {
                float4 k4 = Kr[d];
                s0 = fmaf(q[4*d+0], k4.x, s0);
                s1 = fmaf(q[4*d+1], k4.y, s1);
                s2 = fmaf(q[4*d+2], k4.z, s2);
                s3 = fmaf(q[4*d+3], k4.w, s3);
            }
            float s = (s0 + s1) + (s2 + s3);
            // shift-softmax: uniform scale e^-12 cancels in normalization
            float p = __expf(fmaf(s, 0.125f, -12.0f));
            denom += p;
            const float4* Vr = (const float4*)(Vs + j * HD);
            #pragma unroll
            for (int d = 0; d < 16; d++) {
                float4 v4 = Vr[d];
                acc[4*d+0] = fmaf(p, v4.x, acc[4*d+0]);
                acc[4*d+1] = fmaf(p, v4.y, acc[4*d+1]);
                acc[4*d+2] = fmaf(p, v4.z, acc[4*d+2]);
                acc[4*d+3] = fmaf(p, v4.w, acc[4*d+3]);
            }
        }

        float inv = 1.f / denom;
        float4* Og = (float4*)(g_attn_out + (size_t)(b * NN + tid) * DD + h * HD);
        #pragma unroll
        for (int i = 0; i < 16; i++)
            Og[i] = make_float4(acc[4*i+0]*inv, acc[4*i+1]*inv,
                                acc[4*i+2]*inv, acc[4*i+3]*inv);
    }
}

// ---------------------------------------------------------------------------
extern "C" void kernel_launch(void* const* d_in, const int* in_sizes, int n_in,
                              void* d_out, int out_size)
{
    const float* x            = (const float*)d_in[0];
    const unsigned char* mask = (const unsigned char*)d_in[1];
    const float* in_proj_w    = (const float*)d_in[2];
    const float* in_proj_b    = (const float*)d_in[3];
    const float* out_proj_w   = (const float*)d_in[4];
    const float* out_proj_b   = (const float*)d_in[5];
    float* out = (float*)d_out;

    void* attn_out_ptr = nullptr;
    cudaGetSymbolAddress(&attn_out_ptr, g_attn_out);

    cudaFuncSetAttribute(attn_kernel2,
                         cudaFuncAttributeMaxDynamicSharedMemorySize,
                         ATTN2_SMEM);

    // 1) mask dtype detection
    detect_mask_kernel<<<1, 32>>>(mask);

    // 2) QKV projection -> scattered [3,B,H,N,HD]
    {
        dim3 grid(3 * DD / BN, (MROWS + BM - 1) / BM);
        gemm_nt<<<grid, 256>>>(x, in_proj_w, in_proj_b, nullptr,
                               MROWS, 3 * DD, DD, 1);
    }

    // 3) attention per (b,h)
    attn_kernel2<<<BB * HH, ATTN_THREADS, ATTN2_SMEM>>>(mask);

    // 4) output projection -> d_out
    {
        dim3 grid(DD / BN, (MROWS + BM - 1) / BM);
        gemm_nt<<<grid, 256>>>((const float*)attn_out_ptr, out_proj_w,
                               out_proj_b, out, MROWS, DD, DD, 0);
    }
}

// round 4
// speedup vs baseline: 4.3787x; 2.1656x over previous
#include <cuda_runtime.h>
#include <cuda_bf16.h>
#include <cstdint>
#include <math.h>

// Problem constants
#define BB   64
#define NN   257
#define DD   1024
#define HH   16
#define HD   64
#define MROWS (BB*NN)          // 16448
#define QKV_SLAB ((size_t)BB*HH*NN*HD)
#define KDIM 1024

// GEMM tiling (mma.sync bf16 path — arch-agnostic PTX)
#define BM 128
#define BN 128
#define BK 32
#define NITER (KDIM/BK)        // 32
// smem stage: A_hi, A_mid, B_hi, B_mid each [128][40] bf16 (80B row stride)
#define ROWB 80
#define BUF_BYTES (128*ROWB)   // 10240
#define STAGE (4*BUF_BYTES)    // 40960
#define SMEM_DYN (3*STAGE)     // 122880

// Scratch (device globals — no allocation allowed)
__device__ float g_qkv[3ULL * BB * HH * NN * HD];   // [3,B,H,N,HD]
__device__ float g_attn_out[(size_t)MROWS * DD];    // [B*N, D]
__device__ int   g_mask_mode;
// bf16 split operand buffers (hi + mid)
__device__ __nv_bfloat16 g_xh[(size_t)MROWS * DD], g_xm[(size_t)MROWS * DD];
__device__ __nv_bfloat16 g_ah[(size_t)MROWS * DD], g_am[(size_t)MROWS * DD];
__device__ __nv_bfloat16 g_wh[3 * DD * DD],        g_wm[3 * DD * DD];
__device__ __nv_bfloat16 g_oh[DD * DD],            g_om[DD * DD];

// ---------------------------------------------------------------------------
// PTX helpers (all sm_80-compatible)
// ---------------------------------------------------------------------------
__device__ __forceinline__ uint32_t smem_u32(const void* p) {
    uint32_t a;
    asm("{ .reg .u64 t; cvta.to.shared.u64 t, %1; cvt.u32.u64 %0, t; }"
        : "=r"(a) : "l"(p));
    return a;
}
__device__ __forceinline__ void cp16(uint32_t dst, const void* src, bool pred) {
    int sz = pred ? 16 : 0;
    asm volatile("cp.async.cg.shared.global [%0], [%1], 16, %2;"
                 :: "r"(dst), "l"(src), "r"(sz));
}
#define CP_COMMIT() asm volatile("cp.async.commit_group;")
#define CP_WAIT(n)  asm volatile("cp.async.wait_group %0;" :: "n"(n))

#define LDM4(r, addr) \
    asm volatile("ldmatrix.sync.aligned.m8n8.x4.shared.b16 {%0,%1,%2,%3}, [%4];" \
        : "=r"((r)[0]), "=r"((r)[1]), "=r"((r)[2]), "=r"((r)[3]) : "r"(addr))

#define MMA(c, a, b0, b1) \
    asm volatile("mma.sync.aligned.m16n8k16.row.col.f32.bf16.bf16.f32 " \
        "{%0,%1,%2,%3}, {%4,%5,%6,%7}, {%8,%9}, {%0,%1,%2,%3};" \
        : "+f"((c)[0]), "+f"((c)[1]), "+f"((c)[2]), "+f"((c)[3]) \
        : "r"((a)[0]), "r"((a)[1]), "r"((a)[2]), "r"((a)[3]), "r"(b0), "r"(b1))

// ---------------------------------------------------------------------------
// Mask dtype detector (proven)
// ---------------------------------------------------------------------------
__global__ void detect_mask_kernel(const unsigned char* __restrict__ p) {
    if (threadIdx.x != 0 || blockIdx.x != 0) return;
    bool bf16 = false, f32 = false, u8 = false;
    for (int i = 0; i < 1024; i++) {
        unsigned char v = p[i];
        if (v == 0x3F) {
            if ((i & 3) == 1) bf16 = true; else f32 = true;
        } else if (v == 1 && (i & 3) != 0) {
            u8 = true;
        }
    }
    g_mask_mode = bf16 ? 3 : (f32 ? 2 : (u8 ? 0 : 1));
}

// ---------------------------------------------------------------------------
// Split fp32 -> bf16 hi + bf16 mid (residual)
// ---------------------------------------------------------------------------
__global__ void split_bf16_kernel(const float* __restrict__ src,
                                  __nv_bfloat16* __restrict__ hi,
                                  __nv_bfloat16* __restrict__ mid, int n4) {
    int i = blockIdx.x * blockDim.x + threadIdx.x;
    if (i >= n4) return;
    float4 v = ((const float4*)src)[i];
    __nv_bfloat16 h0 = __float2bfloat16(v.x);
    __nv_bfloat16 h1 = __float2bfloat16(v.y);
    __nv_bfloat16 h2 = __float2bfloat16(v.z);
    __nv_bfloat16 h3 = __float2bfloat16(v.w);
    __nv_bfloat16 m0 = __float2bfloat16(v.x - __bfloat162float(h0));
    __nv_bfloat16 m1 = __float2bfloat16(v.y - __bfloat162float(h1));
    __nv_bfloat16 m2 = __float2bfloat16(v.z - __bfloat162float(h2));
    __nv_bfloat16 m3 = __float2bfloat16(v.w - __bfloat162float(h3));
    ((__nv_bfloat162*)hi)[2*i]     = __halves2bfloat162(h0, h1);
    ((__nv_bfloat162*)hi)[2*i + 1] = __halves2bfloat162(h2, h3);
    ((__nv_bfloat162*)mid)[2*i]     = __halves2bfloat162(m0, m1);
    ((__nv_bfloat162*)mid)[2*i + 1] = __halves2bfloat162(m2, m3);
}

// ---------------------------------------------------------------------------
// bf16x3 GEMM via mma.sync: C[m,e] = sum_k A[m,k]*W[e,k] + bias[e]
// A = Ah + Am, W = Bh + Bm.  acc += Ah*Bh + Ah*Bm + Am*Bh   (fp32 acc)
// 128x128 CTA tile, BK=32, 8 warps (64x32 warp tile), 3-stage cp.async.
// mode 0: C row-major [M, Nn].  mode 1: scatter into g_qkv [3,B,H,N,HD].
// ---------------------------------------------------------------------------
__device__ __forceinline__ void load_stage(
    uint32_t sb, const __nv_bfloat16* __restrict__ Ah,
    const __nv_bfloat16* __restrict__ Am,
    const __nv_bfloat16* __restrict__ Bh,
    const __nv_bfloat16* __restrict__ Bm,
    int kb, int mBase, int nBase, int M, int tid)
{
    const int r = tid >> 2;          // 0..63
    const int c = tid & 3;           // 16B chunk (8 bf16)
    #pragma unroll
    for (int half = 0; half < 2; half++) {
        int row = r + half * 64;
        int gm = mBase + row;
        bool p = gm < M;
        size_t aoff = (size_t)(p ? gm : 0) * KDIM + kb + c * 8;
        uint32_t d = sb + row * ROWB + c * 16;
        cp16(d,                 Ah + aoff, p);
        cp16(d + BUF_BYTES,     Am + aoff, p);
        size_t boff = (size_t)(nBase + row) * KDIM + kb + c * 8;
        cp16(d + 2 * BUF_BYTES, Bh + boff, true);
        cp16(d + 3 * BUF_BYTES, Bm + boff, true);
    }
}

__global__ __launch_bounds__(256)
void gemm_bf16x3(const __nv_bfloat16* __restrict__ Ah,
                 const __nv_bfloat16* __restrict__ Am,
                 const __nv_bfloat16* __restrict__ Bh,
                 const __nv_bfloat16* __restrict__ Bm,
                 const float* __restrict__ bias, float* __restrict__ C,
                 int M, int Nn, int mode)
{
    extern __shared__ __align__(128) char smem[];
    const uint32_t smb = smem_u32(smem);

    const int tid  = threadIdx.x;
    const int warp = tid >> 5;
    const int lane = tid & 31;
    const int warpM = warp & 1;       // 0..1 -> m offset *64
    const int warpN = warp >> 1;      // 0..3 -> n offset *32
    const int mBase = blockIdx.y * BM;
    const int nBase = blockIdx.x * BN;

    // ldmatrix address bases (byte offsets within a stage)
    const int rowA = warpM * 64 + (lane & 15);
    const int aBase = rowA * ROWB + (lane >> 4) * 16;
    const int rowB = warpN * 32 + ((lane >> 4) << 3) + (lane & 7);
    const int bBase = 2 * BUF_BYTES + rowB * ROWB + (((lane >> 3) & 1) * 16);

    float acc[4][4][4];
    #pragma unroll
    for (int i = 0; i < 4; i++)
        #pragma unroll
        for (int j = 0; j < 4; j++)
            #pragma unroll
            for (int u = 0; u < 4; u++) acc[i][j][u] = 0.f;

    // Prologue: stages 0, 1
    load_stage(smb,         Ah, Am, Bh, Bm, 0,  mBase, nBase, M, tid);
    CP_COMMIT();
    load_stage(smb + STAGE, Ah, Am, Bh, Bm, BK, mBase, nBase, M, tid);
    CP_COMMIT();

    for (int it = 0; it < NITER; it++) {
        if (it < NITER - 1) { CP_WAIT(1); } else { CP_WAIT(0); }
        __syncthreads();
        if (it + 2 < NITER) {
            load_stage(smb + ((it + 2) % 3) * STAGE, Ah, Am, Bh, Bm,
                       (it + 2) * BK, mBase, nBase, M, tid);
            CP_COMMIT();
        }
        const uint32_t sb = smb + (it % 3) * STAGE;

        #pragma unroll
        for (int ks = 0; ks < 2; ks++) {
            uint32_t fAh[4][4], fAm[4][4], fBh[2][4], fBm[2][4];
            #pragma unroll
            for (int mt = 0; mt < 4; mt++) {
                LDM4(fAh[mt], sb + aBase + mt * (16 * ROWB) + ks * 32);
                LDM4(fAm[mt], sb + aBase + mt * (16 * ROWB) + ks * 32 + BUF_BYTES);
            }
            #pragma unroll
            for (int np = 0; np < 2; np++) {
                LDM4(fBh[np], sb + bBase + np * (16 * ROWB) + ks * 32);
                LDM4(fBm[np], sb + bBase + np * (16 * ROWB) + ks * 32 + BUF_BYTES);
            }
            #pragma unroll
            for (int mt = 0; mt < 4; mt++) {
                #pragma unroll
                for (int nt = 0; nt < 4; nt++) {
                    const int np = nt >> 1, bi = (nt & 1) * 2;
                    MMA(acc[mt][nt], fAh[mt], fBh[np][bi], fBh[np][bi + 1]);
                    MMA(acc[mt][nt], fAh[mt], fBm[np][bi], fBm[np][bi + 1]);
                    MMA(acc[mt][nt], fAm[mt], fBh[np][bi], fBh[np][bi + 1]);
                }
            }
        }
        __syncthreads();
    }

    // Epilogue
    const int g = lane >> 2, tig = lane & 3;
    #pragma unroll
    for (int mt = 0; mt < 4; mt++) {
        int m0 = mBase + warpM * 64 + mt * 16 + g;
        int m1 = m0 + 8;
        int b0i = 0, n0i = 0, b1i = 0, n1i = 0;
        if (mode) {
            b0i = m0 / NN; n0i = m0 - b0i * NN;
            b1i = m1 / NN; n1i = m1 - b1i * NN;
        }
        #pragma unroll
        for (int nt = 0; nt < 4; nt++) {
            int e = nBase + warpN * 32 + nt * 8 + tig * 2;
            float bv0 = bias[e], bv1 = bias[e + 1];
            float2 r0 = make_float2(acc[mt][nt][0] + bv0, acc[mt][nt][1] + bv1);
            float2 r1 = make_float2(acc[mt][nt][2] + bv0, acc[mt][nt][3] + bv1);
            if (mode == 0) {
                if (m0 < M) *(float2*)(C + (size_t)m0 * Nn + e) = r0;
                if (m1 < M) *(float2*)(C + (size_t)m1 * Nn + e) = r1;
            } else {
                int qi = e >> 10, h = (e >> 6) & 15, hd = e & 63;
                size_t base = (((size_t)qi * BB) * HH + h) * NN * HD + hd;
                if (m0 < M)
                    *(float2*)(g_qkv + base + ((size_t)b0i * HH * NN + n0i) * HD) = r0;
                if (m1 < M)
                    *(float2*)(g_qkv + base + ((size_t)b1i * HH * NN + n1i) * HD) = r1;
            }
        }
    }
}

// ---------------------------------------------------------------------------
// Attention (proven round-2 version): one thread per query, key compaction,
// shift-softmax.
// ---------------------------------------------------------------------------
#define ATTN_THREADS 288
#define ATTN2_SMEM ((2 * NN * HD + NN + 8) * (int)sizeof(float))

__global__ __launch_bounds__(ATTN_THREADS, 1)
void attn_kernel2(const unsigned char* __restrict__ mask_raw)
{
    extern __shared__ float sh[];
    float* Ks   = sh;
    float* Vs   = sh + NN * HD;
    int*   idxl = (int*)(sh + 2 * NN * HD);
    __shared__ int s_nact;

    const int tid = threadIdx.x;
    const int bh  = blockIdx.x;
    const int b   = bh >> 4;
    const int h   = bh & 15;

    const float* Qg = g_qkv + ((size_t)b * HH + h) * NN * HD;
    const float* Kg = Qg + QKV_SLAB;
    const float* Vg = Kg + QKV_SLAB;

    for (int i = tid; i < NN * (HD / 4); i += ATTN_THREADS) {
        ((float4*)Ks)[i] = ((const float4*)Kg)[i];
        ((float4*)Vs)[i] = ((const float4*)Vg)[i];
    }

    if (tid < 32) {
        const int mode = g_mask_mode;
        int count = 0;
        for (int base = 0; base < NN; base += 32) {
            int j = base + tid;
            bool act = false;
            if (j < NN) {
                int idx = b * NN + j;
                bool mm;
                if      (mode == 0) mm = mask_raw[idx] != 0;
                else if (mode == 1) mm = ((const int*)mask_raw)[idx] != 0;
                else if (mode == 2) mm = ((const float*)mask_raw)[idx] != 0.f;
                else                mm = ((const unsigned short*)mask_raw)[idx] != 0;
                act = !mm;
            }
            unsigned bal = __ballot_sync(0xffffffffu, act);
            int pre = __popc(bal & ((1u << tid) - 1u));
            if (act) idxl[count + pre] = j;
            count += __popc(bal);
        }
        if (tid == 0) s_nact = count;
    }
    __syncthreads();
    const int nact = s_nact;

    if (tid < NN) {
        float q[64];
        const float4* Qr = (const float4*)(Qg + tid * HD);
        #pragma unroll
        for (int i = 0; i < 16; i++) {
            float4 t4 = Qr[i];
            q[4*i] = t4.x; q[4*i+1] = t4.y; q[4*i+2] = t4.z; q[4*i+3] = t4.w;
        }
        float acc[64];
        #pragma unroll
        for (int i = 0; i < 64; i++) acc[i] = 0.f;
        float denom = 0.f;

        for (int ii = 0; ii < nact; ii++) {
            int j = idxl[ii];
            const float4* Kr = (const float4*)(Ks + j * HD);
            float s0 = 0.f, s1 = 0.f, s2 = 0.f, s3 = 0.f;
            #pragma unroll
            for (int d = 0; d < 16; d++) {
                float4 k4 = Kr[d];
                s0 = fmaf(q[4*d+0], k4.x, s0);
                s1 = fmaf(q[4*d+1], k4.y, s1);
                s2 = fmaf(q[4*d+2], k4.z, s2);
                s3 = fmaf(q[4*d+3], k4.w, s3);
            }
            float s = (s0 + s1) + (s2 + s3);
            float p = __expf(fmaf(s, 0.125f, -12.0f));
            denom += p;
            const float4* Vr = (const float4*)(Vs + j * HD);
            #pragma unroll
            for (int d = 0; d < 16; d++) {
                float4 v4 = Vr[d];
                acc[4*d+0] = fmaf(p, v4.x, acc[4*d+0]);
                acc[4*d+1] = fmaf(p, v4.y, acc[4*d+1]);
                acc[4*d+2] = fmaf(p, v4.z, acc[4*d+2]);
                acc[4*d+3] = fmaf(p, v4.w, acc[4*d+3]);
            }
        }

        float inv = 1.f / denom;
        float4* Og = (float4*)(g_attn_out + (size_t)(b * NN + tid) * DD + h * HD);
        #pragma unroll
        for (int i = 0; i < 16; i++)
            Og[i] = make_float4(acc[4*i+0]*inv, acc[4*i+1]*inv,
                                acc[4*i+2]*inv, acc[4*i+3]*inv);
    }
}

// ---------------------------------------------------------------------------
// Host
// ---------------------------------------------------------------------------
extern "C" void kernel_launch(void* const* d_in, const int* in_sizes, int n_in,
                              void* d_out, int out_size)
{
    const float* x            = (const float*)d_in[0];
    const unsigned char* mask = (const unsigned char*)d_in[1];
    const float* in_proj_w    = (const float*)d_in[2];
    const float* in_proj_b    = (const float*)d_in[3];
    const float* out_proj_w   = (const float*)d_in[4];
    const float* out_proj_b   = (const float*)d_in[5];
    float* out = (float*)d_out;

    void *xh, *xm, *ah, *am, *wh, *wm, *oh, *om, *attn_out;
    cudaGetSymbolAddress(&xh, g_xh);  cudaGetSymbolAddress(&xm, g_xm);
    cudaGetSymbolAddress(&ah, g_ah);  cudaGetSymbolAddress(&am, g_am);
    cudaGetSymbolAddress(&wh, g_wh);  cudaGetSymbolAddress(&wm, g_wm);
    cudaGetSymbolAddress(&oh, g_oh);  cudaGetSymbolAddress(&om, g_om);
    cudaGetSymbolAddress(&attn_out, g_attn_out);

    static bool attr_set = false;
    if (!attr_set) {
        cudaFuncSetAttribute(gemm_bf16x3, cudaFuncAttributeMaxDynamicSharedMemorySize, SMEM_DYN);
        cudaFuncSetAttribute(attn_kernel2, cudaFuncAttributeMaxDynamicSharedMemorySize, ATTN2_SMEM);
        attr_set = true;
    }

    // 1) mask dtype detection
    detect_mask_kernel<<<1, 32>>>(mask);

    // 2) split x and weights into bf16 hi/mid
    split_bf16_kernel<<<(MROWS * DD / 4 + 255) / 256, 256>>>(
        x, (__nv_bfloat16*)xh, (__nv_bfloat16*)xm, MROWS * DD / 4);
    split_bf16_kernel<<<(3 * DD * DD / 4 + 255) / 256, 256>>>(
        in_proj_w, (__nv_bfloat16*)wh, (__nv_bfloat16*)wm, 3 * DD * DD / 4);
    split_bf16_kernel<<<(DD * DD / 4 + 255) / 256, 256>>>(
        out_proj_w, (__nv_bfloat16*)oh, (__nv_bfloat16*)om, DD * DD / 4);

    // 3) QKV projection (bf16x3 tensor) -> scatter into g_qkv
    gemm_bf16x3<<<dim3(3 * DD / BN, (MROWS + BM - 1) / BM), 256, SMEM_DYN>>>(
        (const __nv_bfloat16*)xh, (const __nv_bfloat16*)xm,
        (const __nv_bfloat16*)wh, (const __nv_bfloat16*)wm,
        in_proj_b, nullptr, MROWS, 3 * DD, 1);

    // 4) attention
    attn_kernel2<<<BB * HH, ATTN_THREADS, ATTN2_SMEM>>>(mask);

    // 5) split attention output
    split_bf16_kernel<<<(MROWS * DD / 4 + 255) / 256, 256>>>(
        (const float*)attn_out, (__nv_bfloat16*)ah, (__nv_bfloat16*)am, MROWS * DD / 4);

    // 6) output projection -> d_out
    gemm_bf16x3<<<dim3(DD / BN, (MROWS + BM - 1) / BM), 256, SMEM_DYN>>>(
        (const __nv_bfloat16*)ah, (const __nv_bfloat16*)am,
        (const __nv_bfloat16*)oh, (const __nv_bfloat16*)om,
        out_proj_b, out, MROWS, DD, 0);
}

// round 5
// speedup vs baseline: 4.9950x; 1.1408x over previous
#include <cuda_runtime.h>
#include <cuda_bf16.h>
#include <cstdint>
#include <math.h>

// Problem constants
#define BB   64
#define NN   257
#define DD   1024
#define HH   16
#define HD   64
#define MROWS (BB*NN)          // 16448
#define QKV_SLAB ((size_t)BB*HH*NN*HD)
#define KDIM 1024

// GEMM tiling (mma.sync bf16 path — arch-agnostic PTX)
#define BM 128
#define BN 128
#define BK 32
#define NITER (KDIM/BK)        // 32
// smem stage: A_hi, A_mid, B_hi, B_mid each [128][40] bf16 (80B row stride)
#define ROWB 80
#define BUF_BYTES (128*ROWB)   // 10240
#define STAGE (4*BUF_BYTES)    // 40960
#define SMEM_DYN (2*STAGE)     // 81920 -> 2 CTAs/SM

// Scratch (device globals — no allocation allowed)
__device__ float g_qkv[3ULL * BB * HH * NN * HD];   // [3,B,H,N,HD]
__device__ float g_attn_out[(size_t)MROWS * DD];    // [B*N, D]
__device__ int   g_mask_mode;
// bf16 split operand buffers (hi + mid)
__device__ __nv_bfloat16 g_xh[(size_t)MROWS * DD], g_xm[(size_t)MROWS * DD];
__device__ __nv_bfloat16 g_ah[(size_t)MROWS * DD], g_am[(size_t)MROWS * DD];
__device__ __nv_bfloat16 g_wh[3 * DD * DD],        g_wm[3 * DD * DD];
__device__ __nv_bfloat16 g_oh[DD * DD],            g_om[DD * DD];

// ---------------------------------------------------------------------------
// PTX helpers (all sm_80-compatible)
// ---------------------------------------------------------------------------
__device__ __forceinline__ uint32_t smem_u32(const void* p) {
    uint32_t a;
    asm("{ .reg .u64 t; cvta.to.shared.u64 t, %1; cvt.u32.u64 %0, t; }"
        : "=r"(a) : "l"(p));
    return a;
}
__device__ __forceinline__ void cp16(uint32_t dst, const void* src, bool pred) {
    int sz = pred ? 16 : 0;
    asm volatile("cp.async.cg.shared.global [%0], [%1], 16, %2;"
                 :: "r"(dst), "l"(src), "r"(sz));
}
#define CP_COMMIT() asm volatile("cp.async.commit_group;")
#define CP_WAIT(n)  asm volatile("cp.async.wait_group %0;" :: "n"(n))

#define LDM4(r, addr) \
    asm volatile("ldmatrix.sync.aligned.m8n8.x4.shared.b16 {%0,%1,%2,%3}, [%4];" \
        : "=r"((r)[0]), "=r"((r)[1]), "=r"((r)[2]), "=r"((r)[3]) : "r"(addr))

#define MMA(c, a, b0, b1) \
    asm volatile("mma.sync.aligned.m16n8k16.row.col.f32.bf16.bf16.f32 " \
        "{%0,%1,%2,%3}, {%4,%5,%6,%7}, {%8,%9}, {%0,%1,%2,%3};" \
        : "+f"((c)[0]), "+f"((c)[1]), "+f"((c)[2]), "+f"((c)[3]) \
        : "r"((a)[0]), "r"((a)[1]), "r"((a)[2]), "r"((a)[3]), "r"(b0), "r"(b1))

// ---------------------------------------------------------------------------
// Mask dtype detector (proven)
// ---------------------------------------------------------------------------
__global__ void detect_mask_kernel(const unsigned char* __restrict__ p) {
    if (threadIdx.x != 0 || blockIdx.x != 0) return;
    bool bf16 = false, f32 = false, u8 = false;
    for (int i = 0; i < 1024; i++) {
        unsigned char v = p[i];
        if (v == 0x3F) {
            if ((i & 3) == 1) bf16 = true; else f32 = true;
        } else if (v == 1 && (i & 3) != 0) {
            u8 = true;
        }
    }
    g_mask_mode = bf16 ? 3 : (f32 ? 2 : (u8 ? 0 : 1));
}

// ---------------------------------------------------------------------------
// Split fp32 -> bf16 hi + bf16 mid (residual)
// ---------------------------------------------------------------------------
__global__ void split_bf16_kernel(const float* __restrict__ src,
                                  __nv_bfloat16* __restrict__ hi,
                                  __nv_bfloat16* __restrict__ mid, int n4) {
    int i = blockIdx.x * blockDim.x + threadIdx.x;
    if (i >= n4) return;
    float4 v = ((const float4*)src)[i];
    __nv_bfloat16 h0 = __float2bfloat16(v.x);
    __nv_bfloat16 h1 = __float2bfloat16(v.y);
    __nv_bfloat16 h2 = __float2bfloat16(v.z);
    __nv_bfloat16 h3 = __float2bfloat16(v.w);
    __nv_bfloat16 m0 = __float2bfloat16(v.x - __bfloat162float(h0));
    __nv_bfloat16 m1 = __float2bfloat16(v.y - __bfloat162float(h1));
    __nv_bfloat16 m2 = __float2bfloat16(v.z - __bfloat162float(h2));
    __nv_bfloat16 m3 = __float2bfloat16(v.w - __bfloat162float(h3));
    ((__nv_bfloat162*)hi)[2*i]     = __halves2bfloat162(h0, h1);
    ((__nv_bfloat162*)hi)[2*i + 1] = __halves2bfloat162(h2, h3);
    ((__nv_bfloat162*)mid)[2*i]     = __halves2bfloat162(m0, m1);
    ((__nv_bfloat162*)mid)[2*i + 1] = __halves2bfloat162(m2, m3);
}

// ---------------------------------------------------------------------------
// bf16x3 GEMM via mma.sync: C[m,e] = sum_k A[m,k]*W[e,k] + bias[e]
// 128x128 CTA tile, BK=32, 8 warps (64x32 warp tile), 2-stage cp.async,
// 2 CTAs/SM. mode 0: C row-major. mode 1: scatter into g_qkv [3,B,H,N,HD].
// ---------------------------------------------------------------------------
__device__ __forceinline__ void load_stage(
    uint32_t sb, const __nv_bfloat16* __restrict__ Ah,
    const __nv_bfloat16* __restrict__ Am,
    const __nv_bfloat16* __restrict__ Bh,
    const __nv_bfloat16* __restrict__ Bm,
    int kb, int mBase, int nBase, int M, int tid)
{
    const int r = tid >> 2;          // 0..63
    const int c = tid & 3;           // 16B chunk (8 bf16)
    #pragma unroll
    for (int half = 0; half < 2; half++) {
        int row = r + half * 64;
        int gm = mBase + row;
        bool p = gm < M;
        size_t aoff = (size_t)(p ? gm : 0) * KDIM + kb + c * 8;
        uint32_t d = sb + row * ROWB + c * 16;
        cp16(d,                 Ah + aoff, p);
        cp16(d + BUF_BYTES,     Am + aoff, p);
        size_t boff = (size_t)(nBase + row) * KDIM + kb + c * 8;
        cp16(d + 2 * BUF_BYTES, Bh + boff, true);
        cp16(d + 3 * BUF_BYTES, Bm + boff, true);
    }
}

__global__ __launch_bounds__(256, 2)
void gemm_bf16x3(const __nv_bfloat16* __restrict__ Ah,
                 const __nv_bfloat16* __restrict__ Am,
                 const __nv_bfloat16* __restrict__ Bh,
                 const __nv_bfloat16* __restrict__ Bm,
                 const float* __restrict__ bias, float* __restrict__ C,
                 int M, int Nn, int mode)
{
    extern __shared__ __align__(128) char smem[];
    const uint32_t smb = smem_u32(smem);

    const int tid  = threadIdx.x;
    const int warp = tid >> 5;
    const int lane = tid & 31;
    const int warpM = warp & 1;       // 0..1 -> m offset *64
    const int warpN = warp >> 1;      // 0..3 -> n offset *32
    const int mBase = blockIdx.y * BM;
    const int nBase = blockIdx.x * BN;

    // ldmatrix address bases (byte offsets within a stage)
    const int rowA = warpM * 64 + (lane & 15);
    const int aBase = rowA * ROWB + (lane >> 4) * 16;
    const int rowB = warpN * 32 + ((lane >> 4) << 3) + (lane & 7);
    const int bBase = 2 * BUF_BYTES + rowB * ROWB + (((lane >> 3) & 1) * 16);

    float acc[4][4][4];
    #pragma unroll
    for (int i = 0; i < 4; i++)
        #pragma unroll
        for (int j = 0; j < 4; j++)
            #pragma unroll
            for (int u = 0; u < 4; u++) acc[i][j][u] = 0.f;

    // Prologue: stage 0
    load_stage(smb, Ah, Am, Bh, Bm, 0, mBase, nBase, M, tid);
    CP_COMMIT();

    for (int it = 0; it < NITER; it++) {
        if (it + 1 < NITER) {
            load_stage(smb + ((it + 1) & 1) * STAGE, Ah, Am, Bh, Bm,
                       (it + 1) * BK, mBase, nBase, M, tid);
            CP_COMMIT();
            CP_WAIT(1);
        } else {
            CP_WAIT(0);
        }
        __syncthreads();
        const uint32_t sb = smb + (it & 1) * STAGE;

        #pragma unroll
        for (int ks = 0; ks < 2; ks++) {
            // B fragments for this ks (16 regs live)
            uint32_t fBh[2][4], fBm[2][4];
            #pragma unroll
            for (int np = 0; np < 2; np++) {
                LDM4(fBh[np], sb + bBase + np * (16 * ROWB) + ks * 32);
                LDM4(fBm[np], sb + bBase + np * (16 * ROWB) + ks * 32 + BUF_BYTES);
            }
            // One A-fragment pair live at a time (8 regs)
            #pragma unroll
            for (int mt = 0; mt < 4; mt++) {
                uint32_t fAh[4], fAm[4];
                LDM4(fAh, sb + aBase + mt * (16 * ROWB) + ks * 32);
                LDM4(fAm, sb + aBase + mt * (16 * ROWB) + ks * 32 + BUF_BYTES);
                #pragma unroll
                for (int nt = 0; nt < 4; nt++) {
                    const int np = nt >> 1, bi = (nt & 1) * 2;
                    MMA(acc[mt][nt], fAh, fBh[np][bi], fBh[np][bi + 1]);
                    MMA(acc[mt][nt], fAh, fBm[np][bi], fBm[np][bi + 1]);
                    MMA(acc[mt][nt], fAm, fBh[np][bi], fBh[np][bi + 1]);
                }
            }
        }
        __syncthreads();
    }

    // Epilogue
    const int g = lane >> 2, tig = lane & 3;
    #pragma unroll
    for (int mt = 0; mt < 4; mt++) {
        int m0 = mBase + warpM * 64 + mt * 16 + g;
        int m1 = m0 + 8;
        int b0i = 0, n0i = 0, b1i = 0, n1i = 0;
        if (mode) {
            b0i = m0 / NN; n0i = m0 - b0i * NN;
            b1i = m1 / NN; n1i = m1 - b1i * NN;
        }
        #pragma unroll
        for (int nt = 0; nt < 4; nt++) {
            int e = nBase + warpN * 32 + nt * 8 + tig * 2;
            float bv0 = bias[e], bv1 = bias[e + 1];
            float2 r0 = make_float2(acc[mt][nt][0] + bv0, acc[mt][nt][1] + bv1);
            float2 r1 = make_float2(acc[mt][nt][2] + bv0, acc[mt][nt][3] + bv1);
            if (mode == 0) {
                if (m0 < M) *(float2*)(C + (size_t)m0 * Nn + e) = r0;
                if (m1 < M) *(float2*)(C + (size_t)m1 * Nn + e) = r1;
            } else {
                int qi = e >> 10, h = (e >> 6) & 15, hd = e & 63;
                size_t base = (((size_t)qi * BB) * HH + h) * NN * HD + hd;
                if (m0 < M)
                    *(float2*)(g_qkv + base + ((size_t)b0i * HH * NN + n0i) * HD) = r0;
                if (m1 < M)
                    *(float2*)(g_qkv + base + ((size_t)b1i * HH * NN + n1i) * HD) = r1;
            }
        }
    }
}

// ---------------------------------------------------------------------------
// Attention (proven round-2 version): one thread per query, key compaction,
// shift-softmax.
// ---------------------------------------------------------------------------
#define ATTN_THREADS 288
#define ATTN2_SMEM ((2 * NN * HD + NN + 8) * (int)sizeof(float))

__global__ __launch_bounds__(ATTN_THREADS, 1)
void attn_kernel2(const unsigned char* __restrict__ mask_raw)
{
    extern __shared__ float sh[];
    float* Ks   = sh;
    float* Vs   = sh + NN * HD;
    int*   idxl = (int*)(sh + 2 * NN * HD);
    __shared__ int s_nact;

    const int tid = threadIdx.x;
    const int bh  = blockIdx.x;
    const int b   = bh >> 4;
    const int h   = bh & 15;

    const float* Qg = g_qkv + ((size_t)b * HH + h) * NN * HD;
    const float* Kg = Qg + QKV_SLAB;
    const float* Vg = Kg + QKV_SLAB;

    for (int i = tid; i < NN * (HD / 4); i += ATTN_THREADS) {
        ((float4*)Ks)[i] = ((const float4*)Kg)[i];
        ((float4*)Vs)[i] = ((const float4*)Vg)[i];
    }

    if (tid < 32) {
        const int mode = g_mask_mode;
        int count = 0;
        for (int base = 0; base < NN; base += 32) {
            int j = base + tid;
            bool act = false;
            if (j < NN) {
                int idx = b * NN + j;
                bool mm;
                if      (mode == 0) mm = mask_raw[idx] != 0;
                else if (mode == 1) mm = ((const int*)mask_raw)[idx] != 0;
                else if (mode == 2) mm = ((const float*)mask_raw)[idx] != 0.f;
                else                mm = ((const unsigned short*)mask_raw)[idx] != 0;
                act = !mm;
            }
            unsigned bal = __ballot_sync(0xffffffffu, act);
            int pre = __popc(bal & ((1u << tid) - 1u));
            if (act) idxl[count + pre] = j;
            count += __popc(bal);
        }
        if (tid == 0) s_nact = count;
    }
    __syncthreads();
    const int nact = s_nact;

    if (tid < NN) {
        float q[64];
        const float4* Qr = (const float4*)(Qg + tid * HD);
        #pragma unroll
        for (int i = 0; i < 16; i++) {
            float4 t4 = Qr[i];
            q[4*i] = t4.x; q[4*i+1] = t4.y; q[4*i+2] = t4.z; q[4*i+3] = t4.w;
        }
        float acc[64];
        #pragma unroll
        for (int i = 0; i < 64; i++) acc[i] = 0.f;
        float denom = 0.f;

        for (int ii = 0; ii < nact; ii++) {
            int j = idxl[ii];
            const float4* Kr = (const float4*)(Ks + j * HD);
            float s0 = 0.f, s1 = 0.f, s2 = 0.f, s3 = 0.f;
            #pragma unroll
            for (int d = 0; d < 16; d++) {
                float4 k4 = Kr[d];
                s0 = fmaf(q[4*d+0], k4.x, s0);
                s1 = fmaf(q[4*d+1], k4.y, s1);
                s2 = fmaf(q[4*d+2], k4.z, s2);
                s3 = fmaf(q[4*d+3], k4.w, s3);
            }
            float s = (s0 + s1) + (s2 + s3);
            float p = __expf(fmaf(s, 0.125f, -12.0f));
            denom += p;
            const float4* Vr = (const float4*)(Vs + j * HD);
            #pragma unroll
            for (int d = 0; d < 16; d++) {
                float4 v4 = Vr[d];
                acc[4*d+0] = fmaf(p, v4.x, acc[4*d+0]);
                acc[4*d+1] = fmaf(p, v4.y, acc[4*d+1]);
                acc[4*d+2] = fmaf(p, v4.z, acc[4*d+2]);
                acc[4*d+3] = fmaf(p, v4.w, acc[4*d+3]);
            }
        }

        float inv = 1.f / denom;
        float4* Og = (float4*)(g_attn_out + (size_t)(b * NN + tid) * DD + h * HD);
        #pragma unroll
        for (int i = 0; i < 16; i++)
            Og[i] = make_float4(acc[4*i+0]*inv, acc[4*i+1]*inv,
                                acc[4*i+2]*inv, acc[4*i+3]*inv);
    }
}

// ---------------------------------------------------------------------------
// Host
// ---------------------------------------------------------------------------
extern "C" void kernel_launch(void* const* d_in, const int* in_sizes, int n_in,
                              void* d_out, int out_size)
{
    const float* x            = (const float*)d_in[0];
    const unsigned char* mask = (const unsigned char*)d_in[1];
    const float* in_proj_w    = (const float*)d_in[2];
    const float* in_proj_b    = (const float*)d_in[3];
    const float* out_proj_w   = (const float*)d_in[4];
    const float* out_proj_b   = (const float*)d_in[5];
    float* out = (float*)d_out;

    void *xh, *xm, *ah, *am, *wh, *wm, *oh, *om, *attn_out;
    cudaGetSymbolAddress(&xh, g_xh);  cudaGetSymbolAddress(&xm, g_xm);
    cudaGetSymbolAddress(&ah, g_ah);  cudaGetSymbolAddress(&am, g_am);
    cudaGetSymbolAddress(&wh, g_wh);  cudaGetSymbolAddress(&wm, g_wm);
    cudaGetSymbolAddress(&oh, g_oh);  cudaGetSymbolAddress(&om, g_om);
    cudaGetSymbolAddress(&attn_out, g_attn_out);

    static bool attr_set = false;
    if (!attr_set) {
        cudaFuncSetAttribute(gemm_bf16x3, cudaFuncAttributeMaxDynamicSharedMemorySize, SMEM_DYN);
        cudaFuncSetAttribute(attn_kernel2, cudaFuncAttributeMaxDynamicSharedMemorySize, ATTN2_SMEM);
        attr_set = true;
    }

    // 1) mask dtype detection
    detect_mask_kernel<<<1, 32>>>(mask);

    // 2) split x and weights into bf16 hi/mid
    split_bf16_kernel<<<(MROWS * DD / 4 + 255) / 256, 256>>>(
        x, (__nv_bfloat16*)xh, (__nv_bfloat16*)xm, MROWS * DD / 4);
    split_bf16_kernel<<<(3 * DD * DD / 4 + 255) / 256, 256>>>(
        in_proj_w, (__nv_bfloat16*)wh, (__nv_bfloat16*)wm, 3 * DD * DD / 4);
    split_bf16_kernel<<<(DD * DD / 4 + 255) / 256, 256>>>(
        out_proj_w, (__nv_bfloat16*)oh, (__nv_bfloat16*)om, DD * DD / 4);

    // 3) QKV projection (bf16x3 tensor) -> scatter into g_qkv
    gemm_bf16x3<<<dim3(3 * DD / BN, (MROWS + BM - 1) / BM), 256, SMEM_DYN>>>(
        (const __nv_bfloat16*)xh, (const __nv_bfloat16*)xm,
        (const __nv_bfloat16*)wh, (const __nv_bfloat16*)wm,
        in_proj_b, nullptr, MROWS, 3 * DD, 1);

    // 4) attention
    attn_kernel2<<<BB * HH, ATTN_THREADS, ATTN2_SMEM>>>(mask);

    // 5) split attention output
    split_bf16_kernel<<<(MROWS * DD / 4 + 255) / 256, 256>>>(
        (const float*)attn_out, (__nv_bfloat16*)ah, (__nv_bfloat16*)am, MROWS * DD / 4);

    // 6) output projection -> d_out
    gemm_bf16x3<<<dim3(DD / BN, (MROWS + BM - 1) / BM), 256, SMEM_DYN>>>(
        (const __nv_bfloat16*)ah, (const __nv_bfloat16*)am,
        (const __nv_bfloat16*)oh, (const __nv_bfloat16*)om,
        out_proj_b, out, MROWS, DD, 0);
}

// round 6
// speedup vs baseline: 5.4738x; 1.0959x over previous
#include <cuda_runtime.h>
#include <cuda_bf16.h>
#include <cstdint>
#include <math.h>

// Problem constants
#define BB   64
#define NN   257
#define DD   1024
#define HH   16
#define HD   64
#define MROWS (BB*NN)          // 16448
#define KDIM 1024
#define NP   264               // padded key stride for V^T (16B aligned rows)

// GEMM tiling (mma.sync bf16 path — arch-agnostic PTX)
#define BM 128
#define BN 128
#define BK 32
#define NITER (KDIM/BK)        // 32
#define ROWB 80
#define BUF_BYTES (128*ROWB)   // 10240
#define STAGE (4*BUF_BYTES)    // 40960
#define SMEM_DYN (2*STAGE)     // 81920 -> 2 CTAs/SM

// Attention tiling
#define AT_ROWB 144            // 64 bf16 = 128B + 16B pad (conflict-free ldmatrix)
// smem layout offsets (bytes)
#define AT_QH 0
#define AT_QM 18432
#define AT_KH 36864
#define AT_KM 46080
#define AT_VH 55296
#define AT_VM 64512
#define AT_PH 73728
#define AT_PM 92160
#define AT_MSK 110592
#define AT_DEN 111872
#define AT_SMEM 112896

// Scratch (device globals — no allocation allowed; zero-initialized)
__device__ int g_mask_mode;
// bf16 split operand buffers for GEMMs
__device__ __nv_bfloat16 g_xh[(size_t)MROWS * DD], g_xm[(size_t)MROWS * DD];
__device__ __nv_bfloat16 g_ah[(size_t)MROWS * DD], g_am[(size_t)MROWS * DD];
__device__ __nv_bfloat16 g_wh[3 * DD * DD],        g_wm[3 * DD * DD];
__device__ __nv_bfloat16 g_oh[DD * DD],            g_om[DD * DD];
// QKV outputs as bf16 hi/mid (Q,K: [B,H,N,64]; V transposed: [B,H,64,NP])
__device__ __nv_bfloat16 g_qh[(size_t)BB*HH*NN*HD], g_qm[(size_t)BB*HH*NN*HD];
__device__ __nv_bfloat16 g_kh[(size_t)BB*HH*NN*HD], g_km[(size_t)BB*HH*NN*HD];
__device__ __nv_bfloat16 g_vh[(size_t)BB*HH*HD*NP], g_vm[(size_t)BB*HH*HD*NP];

// ---------------------------------------------------------------------------
// PTX helpers (all sm_80-compatible)
// ---------------------------------------------------------------------------
__device__ __forceinline__ uint32_t smem_u32(const void* p) {
    uint32_t a;
    asm("{ .reg .u64 t; cvta.to.shared.u64 t, %1; cvt.u32.u64 %0, t; }"
        : "=r"(a) : "l"(p));
    return a;
}
__device__ __forceinline__ void cp16(uint32_t dst, const void* src, bool pred) {
    int sz = pred ? 16 : 0;
    asm volatile("cp.async.cg.shared.global [%0], [%1], 16, %2;"
                 :: "r"(dst), "l"(src), "r"(sz));
}
#define CP_COMMIT() asm volatile("cp.async.commit_group;")
#define CP_WAIT(n)  asm volatile("cp.async.wait_group %0;" :: "n"(n))

#define LDM4(r, addr) \
    asm volatile("ldmatrix.sync.aligned.m8n8.x4.shared.b16 {%0,%1,%2,%3}, [%4];" \
        : "=r"((r)[0]), "=r"((r)[1]), "=r"((r)[2]), "=r"((r)[3]) : "r"(addr))

#define MMA(c, a, b0, b1) \
    asm volatile("mma.sync.aligned.m16n8k16.row.col.f32.bf16.bf16.f32 " \
        "{%0,%1,%2,%3}, {%4,%5,%6,%7}, {%8,%9}, {%0,%1,%2,%3};" \
        : "+f"((c)[0]), "+f"((c)[1]), "+f"((c)[2]), "+f"((c)[3]) \
        : "r"((a)[0]), "r"((a)[1]), "r"((a)[2]), "r"((a)[3]), "r"(b0), "r"(b1))

__device__ __forceinline__ void split2(float x, float y,
                                       __nv_bfloat162* hi, __nv_bfloat162* mid) {
    __nv_bfloat162 h = __float22bfloat162_rn(make_float2(x, y));
    float2 hf = __bfloat1622float2(h);
    *hi = h;
    *mid = __float22bfloat162_rn(make_float2(x - hf.x, y - hf.y));
}

// ---------------------------------------------------------------------------
// Mask dtype detector (proven)
// ---------------------------------------------------------------------------
__global__ void detect_mask_kernel(const unsigned char* __restrict__ p) {
    if (threadIdx.x != 0 || blockIdx.x != 0) return;
    bool bf16 = false, f32 = false, u8 = false;
    for (int i = 0; i < 1024; i++) {
        unsigned char v = p[i];
        if (v == 0x3F) {
            if ((i & 3) == 1) bf16 = true; else f32 = true;
        } else if (v == 1 && (i & 3) != 0) {
            u8 = true;
        }
    }
    g_mask_mode = bf16 ? 3 : (f32 ? 2 : (u8 ? 0 : 1));
}

// ---------------------------------------------------------------------------
// Split fp32 -> bf16 hi + bf16 mid (residual)
// ---------------------------------------------------------------------------
__global__ void split_bf16_kernel(const float* __restrict__ src,
                                  __nv_bfloat16* __restrict__ hi,
                                  __nv_bfloat16* __restrict__ mid, int n4) {
    int i = blockIdx.x * blockDim.x + threadIdx.x;
    if (i >= n4) return;
    float4 v = ((const float4*)src)[i];
    __nv_bfloat162 h0, m0, h1, m1;
    split2(v.x, v.y, &h0, &m0);
    split2(v.z, v.w, &h1, &m1);
    ((__nv_bfloat162*)hi)[2*i]      = h0;
    ((__nv_bfloat162*)hi)[2*i + 1]  = h1;
    ((__nv_bfloat162*)mid)[2*i]     = m0;
    ((__nv_bfloat162*)mid)[2*i + 1] = m1;
}

// ---------------------------------------------------------------------------
// bf16x3 GEMM via mma.sync (proven): C[m,e] = sum_k A[m,k]*W[e,k] + bias[e]
// mode 0: C fp32 row-major. mode 1: split QKV epilogue (bf16 hi/mid, V^T).
// ---------------------------------------------------------------------------
__device__ __forceinline__ void load_stage(
    uint32_t sb, const __nv_bfloat16* __restrict__ Ah,
    const __nv_bfloat16* __restrict__ Am,
    const __nv_bfloat16* __restrict__ Bh,
    const __nv_bfloat16* __restrict__ Bm,
    int kb, int mBase, int nBase, int M, int tid)
{
    const int r = tid >> 2;          // 0..63
    const int c = tid & 3;           // 16B chunk (8 bf16)
    #pragma unroll
    for (int half = 0; half < 2; half++) {
        int row = r + half * 64;
        int gm = mBase + row;
        bool p = gm < M;
        size_t aoff = (size_t)(p ? gm : 0) * KDIM + kb + c * 8;
        uint32_t d = sb + row * ROWB + c * 16;
        cp16(d,                 Ah + aoff, p);
        cp16(d + BUF_BYTES,     Am + aoff, p);
        size_t boff = (size_t)(nBase + row) * KDIM + kb + c * 8;
        cp16(d + 2 * BUF_BYTES, Bh + boff, true);
        cp16(d + 3 * BUF_BYTES, Bm + boff, true);
    }
}

__global__ __launch_bounds__(256, 2)
void gemm_bf16x3(const __nv_bfloat16* __restrict__ Ah,
                 const __nv_bfloat16* __restrict__ Am,
                 const __nv_bfloat16* __restrict__ Bh,
                 const __nv_bfloat16* __restrict__ Bm,
                 const float* __restrict__ bias, float* __restrict__ C,
                 int M, int Nn, int mode)
{
    extern __shared__ __align__(128) char smem[];
    const uint32_t smb = smem_u32(smem);

    const int tid  = threadIdx.x;
    const int warp = tid >> 5;
    const int lane = tid & 31;
    const int warpM = warp & 1;
    const int warpN = warp >> 1;
    const int mBase = blockIdx.y * BM;
    const int nBase = blockIdx.x * BN;

    const int rowA = warpM * 64 + (lane & 15);
    const int aBase = rowA * ROWB + (lane >> 4) * 16;
    const int rowB = warpN * 32 + ((lane >> 4) << 3) + (lane & 7);
    const int bBase = 2 * BUF_BYTES + rowB * ROWB + (((lane >> 3) & 1) * 16);

    float acc[4][4][4];
    #pragma unroll
    for (int i = 0; i < 4; i++)
        #pragma unroll
        for (int j = 0; j < 4; j++)
            #pragma unroll
            for (int u = 0; u < 4; u++) acc[i][j][u] = 0.f;

    load_stage(smb, Ah, Am, Bh, Bm, 0, mBase, nBase, M, tid);
    CP_COMMIT();

    for (int it = 0; it < NITER; it++) {
        if (it + 1 < NITER) {
            load_stage(smb + ((it + 1) & 1) * STAGE, Ah, Am, Bh, Bm,
                       (it + 1) * BK, mBase, nBase, M, tid);
            CP_COMMIT();
            CP_WAIT(1);
        } else {
            CP_WAIT(0);
        }
        __syncthreads();
        const uint32_t sb = smb + (it & 1) * STAGE;

        #pragma unroll
        for (int ks = 0; ks < 2; ks++) {
            uint32_t fBh[2][4], fBm[2][4];
            #pragma unroll
            for (int np = 0; np < 2; np++) {
                LDM4(fBh[np], sb + bBase + np * (16 * ROWB) + ks * 32);
                LDM4(fBm[np], sb + bBase + np * (16 * ROWB) + ks * 32 + BUF_BYTES);
            }
            #pragma unroll
            for (int mt = 0; mt < 4; mt++) {
                uint32_t fAh[4], fAm[4];
                LDM4(fAh, sb + aBase + mt * (16 * ROWB) + ks * 32);
                LDM4(fAm, sb + aBase + mt * (16 * ROWB) + ks * 32 + BUF_BYTES);
                #pragma unroll
                for (int nt = 0; nt < 4; nt++) {
                    const int np = nt >> 1, bi = (nt & 1) * 2;
                    MMA(acc[mt][nt], fAh, fBh[np][bi], fBh[np][bi + 1]);
                    MMA(acc[mt][nt], fAh, fBm[np][bi], fBm[np][bi + 1]);
                    MMA(acc[mt][nt], fAm, fBh[np][bi], fBh[np][bi + 1]);
                }
            }
        }
        __syncthreads();
    }

    // Epilogue
    const int g = lane >> 2, tig = lane & 3;
    #pragma unroll
    for (int mt = 0; mt < 4; mt++) {
        int m0 = mBase + warpM * 64 + mt * 16 + g;
        int m1 = m0 + 8;
        int b0i = 0, n0i = 0, b1i = 0, n1i = 0;
        if (mode) {
            b0i = m0 / NN; n0i = m0 - b0i * NN;
            b1i = m1 / NN; n1i = m1 - b1i * NN;
        }
        #pragma unroll
        for (int nt = 0; nt < 4; nt++) {
            int e = nBase + warpN * 32 + nt * 8 + tig * 2;
            float bv0 = bias[e], bv1 = bias[e + 1];
            float2 r0 = make_float2(acc[mt][nt][0] + bv0, acc[mt][nt][1] + bv1);
            float2 r1 = make_float2(acc[mt][nt][2] + bv0, acc[mt][nt][3] + bv1);
            if (mode == 0) {
                if (m0 < M) *(float2*)(C + (size_t)m0 * Nn + e) = r0;
                if (m1 < M) *(float2*)(C + (size_t)m1 * Nn + e) = r1;
            } else {
                int qi = e >> 10, hh = (e >> 6) & 15, hd = e & 63;
                __nv_bfloat162 h0, mm0, h1, mm1;
                split2(r0.x, r0.y, &h0, &mm0);
                split2(r1.x, r1.y, &h1, &mm1);
                if (qi < 2) {
                    __nv_bfloat16* dh = qi ? g_kh : g_qh;
                    __nv_bfloat16* dm = qi ? g_km : g_qm;
                    if (m0 < M) {
                        size_t o = (((size_t)b0i * HH + hh) * NN + n0i) * HD + hd;
                        *(__nv_bfloat162*)(dh + o) = h0;
                        *(__nv_bfloat162*)(dm + o) = mm0;
                    }
                    if (m1 < M) {
                        size_t o = (((size_t)b1i * HH + hh) * NN + n1i) * HD + hd;
                        *(__nv_bfloat162*)(dh + o) = h1;
                        *(__nv_bfloat162*)(dm + o) = mm1;
                    }
                } else {
                    if (m0 < M) {
                        size_t o = (((size_t)b0i * HH + hh) * HD + hd) * NP + n0i;
                        g_vh[o] = h0.x;  g_vh[o + NP] = h0.y;
                        g_vm[o] = mm0.x; g_vm[o + NP] = mm0.y;
                    }
                    if (m1 < M) {
                        size_t o = (((size_t)b1i * HH + hh) * HD + hd) * NP + n1i;
                        g_vh[o] = h1.x;  g_vh[o + NP] = h1.y;
                        g_vm[o] = mm1.x; g_vm[o + NP] = mm1.y;
                    }
                }
            }
        }
    }
}

// ---------------------------------------------------------------------------
// Tensor-core attention: CTA = (b,h) x 128-query tile, 8 warps.
// Keys in 5 chunks of 64 (zero-padded). Shift softmax p=exp(s/8-12).
// S = QK^T (bf16x3), O += P·V (bf16 P-split x V-split, 3 mma).
// Writes bf16 hi/mid attention output directly for the out-proj GEMM.
// ---------------------------------------------------------------------------
__global__ __launch_bounds__(256, 2)
void attn_tc(const unsigned char* __restrict__ mask_raw)
{
    extern __shared__ __align__(128) char sm[];
    const uint32_t S0 = smem_u32(sm);
    float* msk  = (float*)(sm + AT_MSK);   // [320] additive (-12 active, -1e30 masked/pad)
    float* dsum = (float*)(sm + AT_DEN);   // [2][128]

    const int tid = threadIdx.x;
    const int warp = tid >> 5;
    const int lane = tid & 31;
    const int qw = warp >> 1;      // 0..3: query sub-tile (32 rows)
    const int kw = warp & 1;       // 0..1: key/dim half (32 cols)
    const int g = lane >> 2, tig = lane & 3;

    const int bh = blockIdx.x;
    const int b = bh >> 4, h = bh & 15;
    const int q0 = blockIdx.y * 128;

    const size_t qkbase = ((size_t)b * HH + h) * NN * HD;
    const size_t vbase0 = ((size_t)b * HH + h) * HD * NP;

    // ---- Q tile load (once) ----
    {
        int r = tid >> 1;             // 0..127
        int cpart = (tid & 1) * 4;    // 16B chunks 0-3 / 4-7
        int qg = q0 + r;
        bool p = qg < NN;
        size_t off = qkbase + (size_t)(p ? qg : 0) * HD + cpart * 8;
        uint32_t d = S0 + AT_QH + r * AT_ROWB + cpart * 16;
        #pragma unroll
        for (int u = 0; u < 4; u++) {
            cp16(d + u * 16,                    g_qh + off + u * 8, p);
            cp16(d + u * 16 + (AT_QM - AT_QH),  g_qm + off + u * 8, p);
        }
    }
    CP_COMMIT();

    // ---- mask ----
    {
        const int mode = g_mask_mode;
        for (int j = tid; j < 320; j += 256) {
            float mv = -1e30f;
            if (j < NN) {
                int idx = b * NN + j;
                bool mm;
                if      (mode == 0) mm = mask_raw[idx] != 0;
                else if (mode == 1) mm = ((const int*)mask_raw)[idx] != 0;
                else if (mode == 2) mm = ((const float*)mask_raw)[idx] != 0.f;
                else                mm = ((const unsigned short*)mask_raw)[idx] != 0;
                mv = mm ? -1e30f : -12.0f;
            }
            msk[j] = mv;
        }
    }

    // fragment address bases (relative to each buffer)
    const int aQ = (qw * 32 + (lane & 15)) * AT_ROWB + (lane >> 4) * 16;
    const int bK = (kw * 32 + ((lane >> 4) << 3) + (lane & 7)) * AT_ROWB
                   + ((lane >> 3) & 1) * 16;

    float accO[2][4][4];
    #pragma unroll
    for (int i = 0; i < 2; i++)
        #pragma unroll
        for (int j = 0; j < 4; j++)
            #pragma unroll
            for (int u = 0; u < 4; u++) accO[i][j][u] = 0.f;
    float den[2][2] = {{0.f, 0.f}, {0.f, 0.f}};

    for (int c = 0; c < 5; c++) {
        // ---- load K,V chunk (single buffer) ----
        {
            int r = tid >> 2;            // 0..63 (key row for K, d row for V)
            int cpart = (tid & 3) * 2;   // 2 of 8 16B chunks
            int j = c * 64 + r;
            bool pk = j < NN;
            size_t koff = qkbase + (size_t)(pk ? j : 0) * HD;
            uint32_t dk = S0 + AT_KH + r * AT_ROWB + cpart * 16;
            size_t voff = vbase0 + (size_t)r * NP + c * 64 + cpart * 8;
            uint32_t dv = S0 + AT_VH + r * AT_ROWB + cpart * 16;
            #pragma unroll
            for (int u = 0; u < 2; u++) {
                cp16(dk + u * 16,                    g_kh + koff + (cpart + u) * 8, pk);
                cp16(dk + u * 16 + (AT_KM - AT_KH),  g_km + koff + (cpart + u) * 8, pk);
                bool pv = (c * 64 + (cpart + u) * 8) < NP;
                cp16(dv + u * 16,                    g_vh + voff + u * 8, pv);
                cp16(dv + u * 16 + (AT_VM - AT_VH),  g_vm + voff + u * 8, pv);
            }
        }
        CP_COMMIT();
        CP_WAIT(0);
        __syncthreads();

        // ---- S = Q K^T (bf16x3) ----
        float accS[2][4][4];
        #pragma unroll
        for (int i = 0; i < 2; i++)
            #pragma unroll
            for (int j = 0; j < 4; j++)
                #pragma unroll
                for (int u = 0; u < 4; u++) accS[i][j][u] = 0.f;

        #pragma unroll
        for (int ks = 0; ks < 4; ks++) {
            uint32_t fBh[2][4], fBm[2][4];
            #pragma unroll
            for (int np = 0; np < 2; np++) {
                LDM4(fBh[np], S0 + AT_KH + bK + np * (16 * AT_ROWB) + ks * 32);
                LDM4(fBm[np], S0 + AT_KM + bK + np * (16 * AT_ROWB) + ks * 32);
            }
            #pragma unroll
            for (int mt = 0; mt < 2; mt++) {
                uint32_t fAh[4], fAm[4];
                LDM4(fAh, S0 + AT_QH + aQ + mt * (16 * AT_ROWB) + ks * 32);
                LDM4(fAm, S0 + AT_QM + aQ + mt * (16 * AT_ROWB) + ks * 32);
                #pragma unroll
                for (int nt = 0; nt < 4; nt++) {
                    const int np = nt >> 1, bi = (nt & 1) * 2;
                    MMA(accS[mt][nt], fAh, fBh[np][bi], fBh[np][bi + 1]);
                    MMA(accS[mt][nt], fAh, fBm[np][bi], fBm[np][bi + 1]);
                    MMA(accS[mt][nt], fAm, fBh[np][bi], fBh[np][bi + 1]);
                }
            }
        }

        // ---- exp, denom, P -> bf16 hi/mid in smem ----
        #pragma unroll
        for (int mt = 0; mt < 2; mt++) {
            int row0 = qw * 32 + mt * 16 + g;
            #pragma unroll
            for (int nt = 0; nt < 4; nt++) {
                int col = kw * 32 + nt * 8 + tig * 2;
                int j = c * 64 + col;
                float mv0 = msk[j], mv1 = msk[j + 1];
                float p0 = __expf(fmaf(accS[mt][nt][0], 0.125f, mv0));
                float p1 = __expf(fmaf(accS[mt][nt][1], 0.125f, mv1));
                float p2 = __expf(fmaf(accS[mt][nt][2], 0.125f, mv0));
                float p3 = __expf(fmaf(accS[mt][nt][3], 0.125f, mv1));
                den[mt][0] += p0 + p1;
                den[mt][1] += p2 + p3;
                __nv_bfloat162 h01, m01, h23, m23;
                split2(p0, p1, &h01, &m01);
                split2(p2, p3, &h23, &m23);
                char* ph = sm + AT_PH + row0 * AT_ROWB + col * 2;
                char* pm = sm + AT_PM + row0 * AT_ROWB + col * 2;
                *(__nv_bfloat162*)ph = h01;
                *(__nv_bfloat162*)pm = m01;
                *(__nv_bfloat162*)(ph + 8 * AT_ROWB) = h23;
                *(__nv_bfloat162*)(pm + 8 * AT_ROWB) = m23;
            }
        }
        __syncthreads();

        // ---- O += P V (bf16 split x3) ----
        #pragma unroll
        for (int ks = 0; ks < 4; ks++) {
            uint32_t fBh[2][4], fBm[2][4];
            #pragma unroll
            for (int np = 0; np < 2; np++) {
                LDM4(fBh[np], S0 + AT_VH + bK + np * (16 * AT_ROWB) + ks * 32);
                LDM4(fBm[np], S0 + AT_VM + bK + np * (16 * AT_ROWB) + ks * 32);
            }
            #pragma unroll
            for (int mt = 0; mt < 2; mt++) {
                uint32_t fAh[4], fAm[4];
                LDM4(fAh, S0 + AT_PH + aQ + mt * (16 * AT_ROWB) + ks * 32);
                LDM4(fAm, S0 + AT_PM + aQ + mt * (16 * AT_ROWB) + ks * 32);
                #pragma unroll
                for (int nt = 0; nt < 4; nt++) {
                    const int np = nt >> 1, bi = (nt & 1) * 2;
                    MMA(accO[mt][nt], fAh, fBh[np][bi], fBh[np][bi + 1]);
                    MMA(accO[mt][nt], fAh, fBm[np][bi], fBm[np][bi + 1]);
                    MMA(accO[mt][nt], fAm, fBh[np][bi], fBh[np][bi + 1]);
                }
            }
        }
        __syncthreads();
    }

    // ---- denominator reduce ----
    #pragma unroll
    for (int mt = 0; mt < 2; mt++)
        #pragma unroll
        for (int hf = 0; hf < 2; hf++) {
            float v = den[mt][hf];
            v += __shfl_xor_sync(0xffffffffu, v, 1);
            v += __shfl_xor_sync(0xffffffffu, v, 2);
            if (tig == 0)
                dsum[kw * 128 + qw * 32 + mt * 16 + g + hf * 8] = v;
        }
    __syncthreads();

    // ---- epilogue: scale and write bf16 hi/mid for out-proj ----
    #pragma unroll
    for (int mt = 0; mt < 2; mt++) {
        #pragma unroll
        for (int hf = 0; hf < 2; hf++) {
            int rl = qw * 32 + mt * 16 + g + hf * 8;
            int qg = q0 + rl;
            if (qg < NN) {
                float inv = 1.f / (dsum[rl] + dsum[128 + rl]);
                #pragma unroll
                for (int nt = 0; nt < 4; nt++) {
                    int d = kw * 32 + nt * 8 + tig * 2;
                    float o0 = accO[mt][nt][hf * 2] * inv;
                    float o1 = accO[mt][nt][hf * 2 + 1] * inv;
                    __nv_bfloat162 hv, mv;
                    split2(o0, o1, &hv, &mv);
                    size_t off = ((size_t)(b * NN + qg)) * DD + h * 64 + d;
                    *(__nv_bfloat162*)(g_ah + off) = hv;
                    *(__nv_bfloat162*)(g_am + off) = mv;
                }
            }
        }
    }
}

// ---------------------------------------------------------------------------
// Host
// ---------------------------------------------------------------------------
extern "C" void kernel_launch(void* const* d_in, const int* in_sizes, int n_in,
                              void* d_out, int out_size)
{
    const float* x            = (const float*)d_in[0];
    const unsigned char* mask = (const unsigned char*)d_in[1];
    const float* in_proj_w    = (const float*)d_in[2];
    const float* in_proj_b    = (const float*)d_in[3];
    const float* out_proj_w   = (const float*)d_in[4];
    const float* out_proj_b   = (const float*)d_in[5];
    float* out = (float*)d_out;

    void *xh, *xm, *ah, *am, *wh, *wm, *oh, *om;
    cudaGetSymbolAddress(&xh, g_xh);  cudaGetSymbolAddress(&xm, g_xm);
    cudaGetSymbolAddress(&ah, g_ah);  cudaGetSymbolAddress(&am, g_am);
    cudaGetSymbolAddress(&wh, g_wh);  cudaGetSymbolAddress(&wm, g_wm);
    cudaGetSymbolAddress(&oh, g_oh);  cudaGetSymbolAddress(&om, g_om);

    static bool attr_set = false;
    if (!attr_set) {
        cudaFuncSetAttribute(gemm_bf16x3, cudaFuncAttributeMaxDynamicSharedMemorySize, SMEM_DYN);
        cudaFuncSetAttribute(attn_tc, cudaFuncAttributeMaxDynamicSharedMemorySize, AT_SMEM);
        attr_set = true;
    }

    // 1) mask dtype detection
    detect_mask_kernel<<<1, 32>>>(mask);

    // 2) split x and weights into bf16 hi/mid
    split_bf16_kernel<<<(MROWS * DD / 4 + 255) / 256, 256>>>(
        x, (__nv_bfloat16*)xh, (__nv_bfloat16*)xm, MROWS * DD / 4);
    split_bf16_kernel<<<(3 * DD * DD / 4 + 255) / 256, 256>>>(
        in_proj_w, (__nv_bfloat16*)wh, (__nv_bfloat16*)wm, 3 * DD * DD / 4);
    split_bf16_kernel<<<(DD * DD / 4 + 255) / 256, 256>>>(
        out_proj_w, (__nv_bfloat16*)oh, (__nv_bfloat16*)om, DD * DD / 4);

    // 3) QKV projection -> bf16 hi/mid Q,K and transposed V
    gemm_bf16x3<<<dim3(3 * DD / BN, (MROWS + BM - 1) / BM), 256, SMEM_DYN>>>(
        (const __nv_bfloat16*)xh, (const __nv_bfloat16*)xm,
        (const __nv_bfloat16*)wh, (const __nv_bfloat16*)wm,
        in_proj_b, nullptr, MROWS, 3 * DD, 1);

    // 4) tensor-core attention -> g_ah/g_am (bf16 splits)
    attn_tc<<<dim3(BB * HH, 3), 256, AT_SMEM>>>(mask);

    // 5) output projection -> d_out
    gemm_bf16x3<<<dim3(DD / BN, (MROWS + BM - 1) / BM), 256, SMEM_DYN>>>(
        (const __nv_bfloat16*)ah, (const __nv_bfloat16*)am,
        (const __nv_bfloat16*)oh, (const __nv_bfloat16*)om,
        out_proj_b, out, MROWS, DD, 0);
}